// round 6
// baseline (speedup 1.0000x reference)
#include <cuda_runtime.h>
#include <cuda_fp16.h>
#include <math.h>
#include <stdint.h>

// ---------------- problem constants ----------------
#define Bv 16
#define Nv 128
#define Dv 256
#define Hv 8
#define BM (Bv*Nv)                               // 2048 (b,m) pairs
#define EDGE_ELEMS ((size_t)Bv*Nv*Nv*Dv)         // 67108864
#define INV_SQRT_DK 0.17677669529663688f

// ---------------- device scratch (no runtime alloc) ----------------
__device__ float g_WqT[Dv*Dv];
__device__ float g_WvT[Dv*Dv];
__device__ float g_vproj[(size_t)BM*Dv];          // fp32 v projection
__device__ __half2 g_vprojP[(size_t)Bv*64*Dv];    // n-paired half2: [b][n2][d]
__device__ __half2 g_WnTp[128*Dv];                // j-paired half2: [j2][d]
// B fragments as tile-pairs: [(kt*16 + tp)*32 + lane] = (t0.b0,t0.b1,t1.b0,t1.b1)
__device__ uint4 g_fragK4[16*16*32];
__device__ uint4 g_fragE4[16*16*32];
// per-bm qW score fragments (hi/lo): [bm*512 + kt*32 + lane]
__device__ uint4 g_qWfrag[(size_t)BM*512];

// fast exact-identity mish: x*tanh(log1p(e^x)) == x*(u^2-1)/(u^2+1), u=1+e^x
__device__ __forceinline__ float mishf(float x) {
    if (x > 20.0f) return x;
    float t  = __expf(x);
    float u  = 1.0f + t;
    float u2 = u * u;
    return x * __fdividef(u2 - 1.0f, u2 + 1.0f);
}
__device__ __forceinline__ unsigned h2u(__half a, __half b) {
    return (unsigned)__half_as_ushort(a) | ((unsigned)__half_as_ushort(b) << 16);
}
__device__ __forceinline__ unsigned h2pack(__half2 h) {
    return *reinterpret_cast<unsigned*>(&h);
}
__device__ __forceinline__ uint32_t smem_u32(const void* p) {
    uint32_t a;
    asm("{ .reg .u64 t; cvta.to.shared.u64 t, %1; cvt.u32.u64 %0, t; }" : "=r"(a) : "l"(p));
    return a;
}
__device__ __forceinline__ void mma16816(float* d, const unsigned* a,
                                         unsigned b0, unsigned b1) {
    asm volatile(
        "mma.sync.aligned.m16n8k16.row.col.f32.f16.f16.f32 "
        "{%0,%1,%2,%3},{%4,%5,%6,%7},{%8,%9},{%0,%1,%2,%3};"
        : "+f"(d[0]), "+f"(d[1]), "+f"(d[2]), "+f"(d[3])
        : "r"(a[0]), "r"(a[1]), "r"(a[2]), "r"(a[3]), "r"(b0), "r"(b1));
}
__device__ __forceinline__ void ldsm_x4(unsigned* a, uint32_t addr) {
    asm volatile("ldmatrix.sync.aligned.m8n8.x4.shared.b16 {%0,%1,%2,%3}, [%4];"
        : "=r"(a[0]), "=r"(a[1]), "=r"(a[2]), "=r"(a[3]) : "r"(addr));
}

// hi/lo split helpers
__device__ __forceinline__ void hl_split(float x0, float x1, unsigned& hi, unsigned& lo) {
    __half2 h = __floats2half2_rn(x0, x1);
    float2 r = __half22float2(h);
    __half2 l = __floats2half2_rn(x0 - r.x, x1 - r.y);
    hi = h2pack(h); lo = h2pack(l);
}

// ---------------- smem layout (bytes) ----------------
#define PITCH 264                                 // halfs per row of sA
#define SA_OFF    0                               // 128*264*2 = 67584 (fp16 A / A2)
#define SATTN_OFF 67584                           // 4096
#define SNODE_OFF (SATTN_OFF + 4096)              // 1024
#define SBIAS_OFF (SNODE_OFF + 1024)              // 2048 (bk, be)
#define SMEM_TOTAL (SBIAS_OFF + 2048)             // 74752

// ---------------- K1: all weight prep in one launch (320 blocks x 256) ----------------
// blk 0..63    : transpose Wq -> g_WqT
// blk 64..127  : transpose Wv -> g_WvT
// blk 128..255 : pack WnT j-pairs (half2)
// blk 256..319 : uint4 tile-pair fragments for Wk and We
__global__ void wprep_kernel(const float* __restrict__ Wq, const float* __restrict__ Wv,
                             const float* __restrict__ Wn,
                             const float* __restrict__ Wk, const float* __restrict__ We) {
    int blk = blockIdx.x, tid = threadIdx.x;
    if (blk < 128) {
        int which = blk >> 6, t2 = blk & 63;
        const float* src = (which == 0) ? Wq : Wv;
        float* dst = (which == 0) ? g_WqT : g_WvT;
        __shared__ float t[32][33];
        int x0 = (t2 & 7) * 32, y0 = (t2 >> 3) * 32;
        int tx = tid & 31, ty = tid >> 5;
        #pragma unroll
        for (int i = 0; i < 32; i += 8) t[ty + i][tx] = src[(y0 + ty + i) * Dv + x0 + tx];
        __syncthreads();
        #pragma unroll
        for (int i = 0; i < 32; i += 8) dst[(x0 + ty + i) * Dv + y0 + tx] = t[tx][ty + i];
    } else if (blk < 256) {
        int e = (blk - 128) * 256 + tid;          // 0..32767
        int j2 = e >> 8, d = e & 255;
        g_WnTp[e] = __floats2half2_rn(Wn[d * Dv + 2 * j2], Wn[d * Dv + 2 * j2 + 1]);
    } else {
        int g = (blk - 256) * 256 + tid;          // 0..16383
        int mat = g >> 13;
        int r = g & 8191;
        int kt = r >> 9, tp = (r >> 5) & 15, lane = r & 31;
        const float* W = mat ? We : Wk;
        int k0 = kt * 16 + (lane & 3) * 2;
        int n0 = (2 * tp) * 8 + (lane >> 2);
        int n1 = n0 + 8;
        uint4 f;
        f.x = h2u(__float2half_rn(W[n0 * Dv + k0]),     __float2half_rn(W[n0 * Dv + k0 + 1]));
        f.y = h2u(__float2half_rn(W[n0 * Dv + k0 + 8]), __float2half_rn(W[n0 * Dv + k0 + 9]));
        f.z = h2u(__float2half_rn(W[n1 * Dv + k0]),     __float2half_rn(W[n1 * Dv + k0 + 1]));
        f.w = h2u(__float2half_rn(W[n1 * Dv + k0 + 8]), __float2half_rn(W[n1 * Dv + k0 + 9]));
        if (mat) g_fragE4[r] = f;
        else     g_fragK4[r] = f;
    }
}

// ---------------- K2: per-(b,m) q/v projections + qW score fragments ----------------
__global__ void prep_kernel(const float* __restrict__ qn, const float* __restrict__ vn,
                            const float* __restrict__ Wk,
                            const float* __restrict__ bq, const float* __restrict__ bv) {
    int bm = blockIdx.x, tid = threadIdx.x;
    __shared__ float sRow[Dv];
    __shared__ float sQp[Dv];
    __shared__ float sQ8[8 * 257];
    sRow[tid] = qn[(size_t)bm * Dv + tid];
    __syncthreads();
    float acc = bq[tid];
    for (int j = 0; j < Dv; ++j) acc += sRow[j] * g_WqT[j * Dv + tid];
    sQp[tid] = acc;
    __syncthreads();
    sRow[tid] = vn[(size_t)bm * Dv + tid];
    __syncthreads();
    float accv = bv[tid];
    for (int j = 0; j < Dv; ++j) accv += sRow[j] * g_WvT[j * Dv + tid];
    g_vproj[(size_t)bm * Dv + tid] = accv;
    #pragma unroll
    for (int h = 0; h < Hv; ++h) {
        float a = 0.0f;
        #pragma unroll
        for (int dk = 0; dk < 32; ++dk)
            a += sQp[h * 32 + dk] * Wk[(h * 32 + dk) * Dv + tid];
        sQ8[h * 257 + tid] = a * INV_SQRT_DK;
    }
    __syncthreads();
    // build qW score fragments: B-fragment layout with n-dim = 8 heads
    #pragma unroll
    for (int e = tid; e < 512; e += 256) {
        int kt = e >> 5, lane = e & 31;
        int h = lane >> 2, k0 = kt * 16 + (lane & 3) * 2;
        const float* q = &sQ8[h * 257];
        uint4 f;
        hl_split(q[k0],     q[k0 + 1], f.x, f.z);
        hl_split(q[k0 + 8], q[k0 + 9], f.y, f.w);
        g_qWfrag[(size_t)bm * 512 + e] = f;
    }
}

// ---------------- K3: pack vproj into n-paired half2 ----------------
__global__ void vpack_kernel() {
    int e = blockIdx.x * 256 + threadIdx.x;       // 0..262143
    int d = e & 255, r = e >> 8;                  // r = b*64 + n2
    int b = r >> 6, n2 = r & 63;
    size_t bm0 = (size_t)(b * 128 + 2 * n2) * Dv + d;
    g_vprojP[e] = __floats2half2_rn(g_vproj[bm0], g_vproj[bm0 + Dv]);
}

// One np-pass of a 128x128x256 fp16 GEMM. PF: register double-buffer B prefetch.
template <bool PF>
__device__ __forceinline__ void gemm_pass(float acc[2][8][4], uint32_t lm0, uint32_t lm1,
                                          const uint4* __restrict__ frag, int tpBase, int lane) {
    #pragma unroll
    for (int mi = 0; mi < 2; ++mi)
        #pragma unroll
        for (int t = 0; t < 8; ++t)
            #pragma unroll
            for (int q = 0; q < 4; ++q) acc[mi][t][q] = 0.0f;

    const uint4* fp = frag + (size_t)tpBase * 32 + lane;
    uint4 bf[4];
    if (PF) {
        #pragma unroll
        for (int tp = 0; tp < 4; ++tp) bf[tp] = __ldg(fp + tp * 32);
    }
    #pragma unroll 1
    for (int kt = 0; kt < 16; ++kt) {
        if (!PF) {
            #pragma unroll
            for (int tp = 0; tp < 4; ++tp) bf[tp] = __ldg(fp + kt * 512 + tp * 32);
        }
        unsigned a0[4], a1[4];
        ldsm_x4(a0, lm0 + kt * 32);
        ldsm_x4(a1, lm1 + kt * 32);
        uint4 bfn[4];
        if (PF && kt < 15) {
            #pragma unroll
            for (int tp = 0; tp < 4; ++tp) bfn[tp] = __ldg(fp + (kt + 1) * 512 + tp * 32);
        }
        #pragma unroll
        for (int tp = 0; tp < 4; ++tp) {
            mma16816(acc[0][2 * tp],     a0, bf[tp].x, bf[tp].y);
            mma16816(acc[1][2 * tp],     a1, bf[tp].x, bf[tp].y);
            mma16816(acc[0][2 * tp + 1], a0, bf[tp].z, bf[tp].w);
            mma16816(acc[1][2 * tp + 1], a1, bf[tp].z, bf[tp].w);
        }
        if (PF && kt < 15) {
            #pragma unroll
            for (int tp = 0; tp < 4; ++tp) bf[tp] = bfn[tp];
        }
    }
}

// ---------------- K4: main fused kernel, one CTA per (b,m), 256 threads ----------------
__global__ void __launch_bounds__(256, 2) main_kernel(
    const float* __restrict__ key_edge,
    const float* __restrict__ bk, const float* __restrict__ be,
    const float* __restrict__ bn,
    float* __restrict__ out)
{
    extern __shared__ char sm[];
    __half* sA   = (__half*)(sm + SA_OFF);
    float* sAttn = (float*)(sm + SATTN_OFF);
    float* sNode = (float*)(sm + SNODE_OFF);
    float* sBk   = (float*)(sm + SBIAS_OFF);
    float* sBe   = sBk + 256;

    const int tid = threadIdx.x, lane = tid & 31, warp = tid >> 5;
    const int bm = blockIdx.x, b = bm >> 7;

    sBk[tid] = bk[tid];
    sBe[tid] = be[tid];

    // ---- phase 1: KE (fp32 global) -> sA (fp16) ----
    const float* keb = key_edge + (size_t)bm * (Nv * Dv);
    {
        const int r4 = tid >> 6, c4 = (tid & 63) * 4;
        #pragma unroll 4
        for (int rr = 0; rr < 128; rr += 4) {
            int row = rr + r4;
            float4 v = *(const float4*)&keb[(size_t)row * Dv + c4];
            uint2 p;
            p.x = h2pack(__floats2half2_rn(v.x, v.y));
            p.y = h2pack(__floats2half2_rn(v.z, v.w));
            *(uint2*)&sA[row * PITCH + c4] = p;
        }
    }
    __syncthreads();

    // ldmatrix lane-address helpers
    const int rowsel = (lane & 7) + ((lane >> 3) & 1) * 8;
    const int colsel = (lane >> 4) * 8;
    const uint32_t smbA = smem_u32(sA);

    // ---- phase 2: scores via MMA with pre-baked qW hi/lo fragments ----
    {
        uint32_t lmS = smbA + (uint32_t)(((warp * 16 + rowsel) * PITCH + colsel) * 2);
        const uint4* qf = g_qWfrag + (size_t)bm * 512 + lane;
        float sc[4] = {0.0f, 0.0f, 0.0f, 0.0f};
        uint4 f = __ldg(qf);
        #pragma unroll 1
        for (int kt = 0; kt < 16; ++kt) {
            unsigned a[4];
            ldsm_x4(a, lmS + kt * 32);
            uint4 fn;
            if (kt < 15) fn = __ldg(qf + (kt + 1) * 32);
            mma16816(sc, a, f.x, f.y);   // hi
            mma16816(sc, a, f.z, f.w);   // lo
            if (kt < 15) f = fn;
        }
        int rD = warp * 16 + (lane >> 2);
        int hD = (lane & 3) * 2;
        sAttn[hD * 128 + rD]           = sc[0];
        sAttn[(hD + 1) * 128 + rD]     = sc[1];
        sAttn[hD * 128 + rD + 8]       = sc[2];
        sAttn[(hD + 1) * 128 + rD + 8] = sc[3];
    }
    __syncthreads();

    // ---- softmax (warp per head) ----
    {
        int h = warp;
        float s[4];
        #pragma unroll
        for (int i = 0; i < 4; ++i) s[i] = sAttn[h * 128 + lane + 32 * i];
        float mx = fmaxf(fmaxf(s[0], s[1]), fmaxf(s[2], s[3]));
        #pragma unroll
        for (int off = 16; off > 0; off >>= 1)
            mx = fmaxf(mx, __shfl_xor_sync(0xffffffffu, mx, off));
        float e[4], sum = 0.0f;
        #pragma unroll
        for (int i = 0; i < 4; ++i) { e[i] = __expf(s[i] - mx); sum += e[i]; }
        #pragma unroll
        for (int off = 16; off > 0; off >>= 1)
            sum += __shfl_xor_sync(0xffffffffu, sum, off);
        float inv = __fdividef(1.0f, sum);
        #pragma unroll
        for (int i = 0; i < 4; ++i) sAttn[h * 128 + lane + 32 * i] = e[i] * inv;
    }
    __syncthreads();

    // ---- node path (half2-packed vproj and WnT) ----
    {
        int h = tid >> 5;
        const __half2* vp = g_vprojP + (size_t)b * 64 * Dv + tid;
        const float* att = &sAttn[h * 128];
        float acc = 0.0f;
        #pragma unroll 4
        for (int n2 = 0; n2 < 64; ++n2) {
            float2 v = __half22float2(vp[n2 * Dv]);
            acc += att[2 * n2] * v.x + att[2 * n2 + 1] * v.y;
        }
        sNode[tid] = acc;
        __syncthreads();
        float acc2 = bn[tid];
        #pragma unroll 4
        for (int j2 = 0; j2 < 128; ++j2) {
            float2 w = __half22float2(g_WnTp[j2 * Dv + tid]);
            acc2 += sNode[2 * j2] * w.x + sNode[2 * j2 + 1] * w.y;
        }
        out[EDGE_ELEMS + (size_t)bm * Dv + tid] = mishf(acc2);
    }
    __syncthreads();

    // ---- GEMM setup ----
    const int wi = warp & 3;                 // m-band: rows [wi*32, wi*32+32)
    const int wj = warp >> 2;                // n-group: cols [wj*64, wj*64+64) per np
    const int rA = lane >> 2;                // 0..7
    const int kq = (lane & 3) * 2;           // 0,2,4,6
    const uint32_t lm0 = smbA + (uint32_t)(((wi * 32 + rowsel) * PITCH + colsel) * 2);
    const uint32_t lm1 = lm0 + 16 * PITCH * 2;

    float acc[2][8][4];
    unsigned pk0[2][8][2];

    // ---- GEMM1 np=0 (prefetched) ----
    gemm_pass<true>(acc, lm0, lm1, g_fragK4, 0 * 8 + wj * 4, lane);
    #pragma unroll
    for (int mi = 0; mi < 2; ++mi) {
        #pragma unroll
        for (int t = 0; t < 8; ++t) {
            int r0 = wi * 32 + mi * 16 + rA;
            int c  = wj * 64 + t * 8 + kq;
            float b0 = sBk[c], b1 = sBk[c + 1];
            const float* attc = &sAttn[(c >> 5) * 128];
            float a0 = attc[r0], a8 = attc[r0 + 8];
            pk0[mi][t][0] = h2pack(__floats2half2_rn((acc[mi][t][0] + b0) * a0, (acc[mi][t][1] + b1) * a0));
            pk0[mi][t][1] = h2pack(__floats2half2_rn((acc[mi][t][2] + b0) * a8, (acc[mi][t][3] + b1) * a8));
        }
    }

    // ---- GEMM1 np=1 (no prefetch: pk0 live) ----
    gemm_pass<false>(acc, lm0, lm1, g_fragK4, 1 * 8 + wj * 4, lane);
    __syncthreads();   // all ldmatrix reads of sA (KE) complete

    // write A2 = scaled k (fp16) over sA
    #pragma unroll
    for (int mi = 0; mi < 2; ++mi) {
        #pragma unroll
        for (int t = 0; t < 8; ++t) {
            int r0 = wi * 32 + mi * 16 + rA;
            int c0 = wj * 64 + t * 8 + kq;
            int c1 = 128 + c0;
            *(unsigned*)&sA[r0 * PITCH + c0]       = pk0[mi][t][0];
            *(unsigned*)&sA[(r0 + 8) * PITCH + c0] = pk0[mi][t][1];
            float b0 = sBk[c1], b1 = sBk[c1 + 1];
            const float* attc = &sAttn[(c1 >> 5) * 128];
            float a0 = attc[r0], a8 = attc[r0 + 8];
            *(unsigned*)&sA[r0 * PITCH + c1] =
                h2pack(__floats2half2_rn((acc[mi][t][0] + b0) * a0, (acc[mi][t][1] + b1) * a0));
            *(unsigned*)&sA[(r0 + 8) * PITCH + c1] =
                h2pack(__floats2half2_rn((acc[mi][t][2] + b0) * a8, (acc[mi][t][3] + b1) * a8));
        }
    }
    __syncthreads();   // A2 visible to all warps

    // ---- GEMM2: out = mish(A2 @ We^T + be) ----
    #pragma unroll 1
    for (int np = 0; np < 2; ++np) {
        gemm_pass<true>(acc, lm0, lm1, g_fragE4, np * 8 + wj * 4, lane);
        #pragma unroll
        for (int mi = 0; mi < 2; ++mi) {
            #pragma unroll
            for (int t = 0; t < 8; ++t) {
                int r0 = wi * 32 + mi * 16 + rA;
                int c  = np * 128 + wj * 64 + t * 8 + kq;
                float b0 = sBe[c], b1 = sBe[c + 1];
                float2 o0, o1;
                o0.x = mishf(acc[mi][t][0] + b0);
                o0.y = mishf(acc[mi][t][1] + b1);
                o1.x = mishf(acc[mi][t][2] + b0);
                o1.y = mishf(acc[mi][t][3] + b1);
                *(float2*)&out[((size_t)bm * Nv + r0) * Dv + c]     = o0;
                *(float2*)&out[((size_t)bm * Nv + r0 + 8) * Dv + c] = o1;
            }
        }
    }
}

// ---------------------------------------------------------------------------
extern "C" void kernel_launch(void* const* d_in, const int* in_sizes, int n_in,
                              void* d_out, int out_size) {
    (void)in_sizes; (void)n_in; (void)out_size;
    const float* qn = (const float*)d_in[0];
    const float* vn = (const float*)d_in[1];
    const float* ke = (const float*)d_in[2];
    const float* Wq = (const float*)d_in[4];
    const float* bq = (const float*)d_in[5];
    const float* Wk = (const float*)d_in[6];
    const float* bk = (const float*)d_in[7];
    const float* Wv = (const float*)d_in[8];
    const float* bv = (const float*)d_in[9];
    const float* We = (const float*)d_in[10];
    const float* be = (const float*)d_in[11];
    const float* Wn = (const float*)d_in[12];
    const float* bn = (const float*)d_in[13];
    float* out = (float*)d_out;

    wprep_kernel<<<320, 256>>>(Wq, Wv, Wn, Wk, We);
    prep_kernel<<<BM, 256>>>(qn, vn, Wk, bq, bv);
    vpack_kernel<<<1024, 256>>>();

    cudaFuncSetAttribute(main_kernel, cudaFuncAttributeMaxDynamicSharedMemorySize, SMEM_TOTAL);
    main_kernel<<<BM, 256, SMEM_TOTAL>>>(ke, bk, be, bn, out);
}